// round 16
// baseline (speedup 1.0000x reference)
#include <cuda_runtime.h>
#include <cuda_bf16.h>
#include <math.h>

// pred[b] = sigmoid(gb + data[b,:].bias + || data[b,:] @ embed ||^2)
//   (the (B,F,F) Gram double-sum collapses to the squared norm of s = x @ V)
//
// Grid = 128 blocks (fg 0..15 x bg 0..7), 256 threads, one wave.
// Block (fg, bg): 8 batch rows x 128 features x all 64 dims.
//   - x tile in smem; ALL global loads front-batched (8 embed LDG.128 +
//     4 bias + 1 x) so L2 latency overlaps the x STS/BAR drain
//   - reduce-scatter butterfly over the 16 feature slices (live set halves
//     per round); 2 full-warp spread REDG.ADD emit
//   - TWO-LEVEL warp-granular tickets: each warp acq_rel-arrives on its OWN
//     block's counter (128 distinct lines -> parallel 8-deep chains); the
//     block-last warp resets it and arrives on the group counter (16 ops).
//     Same-address atomic serialization drops 128 -> 8+16 ops.
//     The group-last warp finishes its 8 rows (4 lanes/row) and resets
//     slice + counters (replay-deterministic).

#define F_NUM   2048
#define D_DIM   64
#define BATCH   64
#define THREADS 256
#define BGC     8          // batch groups (8 rows each)
#define FGC     16         // feature groups per batch group
#define FPB     128        // features per block
#define BPB     8          // batch rows per block (== warps per block)

__device__ float        g_s[BATCH][D_DIM];       // zero-init; re-zeroed by finishers
__device__ float        g_lin[BATCH];
__device__ unsigned int g_bcnt[FGC * BGC * 32];  // per-block counter, 1/128B line
__device__ unsigned int g_counter[BGC * 32];     // per-group counter, 1/128B line

__global__ __launch_bounds__(THREADS, 1)
void KTM_22110491640579_kernel(const float* __restrict__ data,
                               const float* __restrict__ embed,
                               const float* __restrict__ bias,
                               const float* __restrict__ gbias,
                               float* __restrict__ out) {
    __shared__ float4 xs4[BPB][FPB / 4];      // 4 KB x tile [8][32 quads]

    const int tid  = threadIdx.x;
    const int fg   = blockIdx.x & (FGC - 1);  // 0..15
    const int bg   = blockIdx.x >> 4;         // 0..7
    const int f0   = fg * FPB;
    const int b0   = bg * BPB;
    const int w    = tid >> 5;                // warp 0..7
    const int lane = tid & 31;

    const int dq = (w << 1) | (lane >> 4);    // 0..15: quad of the s vector
    const int fs = lane & 15;                 // 0..15: 8-feature slice
    const float4* V4 = ((const float4*)embed) + ((size_t)(f0 + fs * 8) * 16 + dq);

    // ---- front-batch ALL global loads (independent addresses, MLP ~13) ----
    float4 ev[8];                             // embed quads for this thread
    #pragma unroll
    for (int j = 0; j < 8; ++j) ev[j] = V4[(size_t)j * 16];
    float bv[4];                              // bias slice for the linear term
    #pragma unroll
    for (int k = 0; k < 4; ++k) bv[k] = bias[f0 + lane + 32 * k];
    const float4 xq =                         // this thread's x quad
        ((const float4*)(data + (size_t)(b0 + w) * F_NUM + f0))[lane];

    // ---- stage x tile: 8 rows x 128 floats ----
    xs4[w][lane] = xq;
    __syncthreads();

    // ---- main loop: v[b*4+c] accumulates s[dq*4+c] for batch row b ----
    float v[32];
    #pragma unroll
    for (int i = 0; i < 32; ++i) v[i] = 0.f;

    #pragma unroll
    for (int jq = 0; jq < 2; ++jq) {          // two float4 groups of 4 features
        float4 xr[BPB];
        #pragma unroll
        for (int b = 0; b < BPB; ++b)
            xr[b] = xs4[b][fs * 2 + jq];      // LDS.128, half-warp broadcast
        #pragma unroll
        for (int jj = 0; jj < 4; ++jj) {
            const float4 vv = ev[jq * 4 + jj];
            #pragma unroll
            for (int b = 0; b < BPB; ++b) {
                const float x = (jj == 0) ? xr[b].x :
                                (jj == 1) ? xr[b].y :
                                (jj == 2) ? xr[b].z : xr[b].w;
                v[b * 4 + 0] = fmaf(x, vv.x, v[b * 4 + 0]);
                v[b * 4 + 1] = fmaf(x, vv.y, v[b * 4 + 1]);
                v[b * 4 + 2] = fmaf(x, vv.z, v[b * 4 + 2]);
                v[b * 4 + 3] = fmaf(x, vv.w, v[b * 4 + 3]);
            }
        }
    }

    // ---- linear term: warp w handles batch row w, full-warp shfl reduce ----
    {
        const float* xsf = (const float*)xs4; // [b][f], stride 128
        float l = 0.f;
        #pragma unroll
        for (int k = 0; k < 4; ++k)
            l = fmaf(xsf[w * FPB + lane + 32 * k], bv[k], l);
        #pragma unroll
        for (int off = 16; off >= 1; off >>= 1)
            l += __shfl_down_sync(0xffffffffu, l, off);
        if (lane == 0) atomicAdd(&g_lin[b0 + w], l);  // relaxed RED.ADD
    }

    // ---- reduce-scatter over fs (lane bits 0..3): live set halves/round ----
    // After the 4 rounds, lane fs holds batch row fs>>1, components
    // (fs&1)*2 + {0,1} of its dq quad.
    #pragma unroll
    for (int off = 8, n = 16; off >= 1; off >>= 1, n >>= 1) {
        const bool up = (fs & off) != 0;
        #pragma unroll
        for (int i = 0; i < 16; ++i) {        // only i < n is live
            if (i < n) {
                const float s = up ? v[i + n] : v[i];
                v[i] = s + __shfl_xor_sync(0xffffffffu, s, off);
            }
        }
    }
    {
        float* dst = &g_s[b0 + (fs >> 1)][dq * 4 + (fs & 1) * 2];
        atomicAdd(dst + 0, v[0]);             // full-warp spread REDG.ADD
        atomicAdd(dst + 1, v[1]);
    }

    // ---- level 1: warp arrives on its OWN block's counter (no contention
    //      across blocks; 8-deep same-address chain only) ----
    __syncwarp();                             // order this warp's REDs
    unsigned int t1 = 0u;
    if (lane == 0) {
        asm volatile("atom.acq_rel.gpu.global.add.u32 %0, [%1], 1;"
                     : "=r"(t1) : "l"(&g_bcnt[blockIdx.x * 32]) : "memory");
    }
    t1 = __shfl_sync(0xffffffffu, t1, 0);
    if (t1 != (unsigned)(BPB - 1)) return;

    // ---- level 2: block-last warp arrives on the group counter (16 ops) ----
    unsigned int t2 = 0u;
    if (lane == 0) {
        g_bcnt[blockIdx.x * 32] = 0u;         // reset for next replay
        asm volatile("atom.acq_rel.gpu.global.add.u32 %0, [%1], 1;"
                     : "=r"(t2) : "l"(&g_counter[bg * 32]) : "memory");
    }
    t2 = __shfl_sync(0xffffffffu, t2, 0);
    if (t2 != (unsigned)(FGC - 1)) return;
    __syncwarp();                             // publish lane0's acquire

    // ---- finisher WARP: 8 rows, 4 lanes per row (16 dims each) ----
    {
        const int r = lane >> 2;              // 0..7 -> batch row b0+r
        const int p = lane & 3;               // 0..3 -> dims p*16..p*16+15
        const int b = b0 + r;
        const float lin_b = __ldcg(&g_lin[b]);
        const float gb    = __ldcg(&gbias[0]);
        const float4* sp  = ((const float4*)g_s[b]) + p * 4;
        float ss = 0.f;
        #pragma unroll
        for (int k = 0; k < 4; ++k) {
            const float4 q = __ldcg(sp + k);
            ss = fmaf(q.x, q.x, ss);
            ss = fmaf(q.y, q.y, ss);
            ss = fmaf(q.z, q.z, ss);
            ss = fmaf(q.w, q.w, ss);
        }
        ss += __shfl_xor_sync(0xffffffffu, ss, 1);
        ss += __shfl_xor_sync(0xffffffffu, ss, 2);
        if (p == 0) {
            const float z = gb + lin_b + ss;
            out[b] = 1.0f / (1.0f + __expf(-z));
            g_lin[b] = 0.f;                   // reset for next replay
        }
        float4* rp = ((float4*)g_s[b]) + p * 4;
        const float4 z4 = make_float4(0.f, 0.f, 0.f, 0.f);
        #pragma unroll
        for (int k = 0; k < 4; ++k) rp[k] = z4;  // reset s slice
        if (lane == 0) g_counter[bg * 32] = 0u;
    }
}

extern "C" void kernel_launch(void* const* d_in, const int* in_sizes, int n_in,
                              void* d_out, int out_size) {
    const float* data  = (const float*)d_in[0];   // (64, 2048)
    const float* embed = (const float*)d_in[1];   // (2048, 64)
    const float* bias  = (const float*)d_in[2];   // (2048, 1)
    const float* gb    = (const float*)d_in[3];   // (1, 1)
    float* out = (float*)d_out;                   // (64,)
    (void)in_sizes; (void)n_in; (void)out_size;

    KTM_22110491640579_kernel<<<FGC * BGC, THREADS>>>(data, embed, bias, gb, out);
}